// round 16
// baseline (speedup 1.0000x reference)
#include <cuda_runtime.h>
#include <cuda_fp16.h>
#include <math.h>
#include <stdint.h>

// ---------------- problem constants ----------------
#define BB   16
#define TT   512
#define NTOK (BB*TT)        // 8192
#define DD   1024
#define HH   16
#define HDIM 64
#define LL   12
#define DFF  4096
#define V0   1025
#define TOUT 511
#define NHEADROWS (BB*TOUT) // 8176
#define NHPAD 1152          // head N padded to 9*128

// ---------------- scratch (device globals; no allocation allowed) -------
__device__ float  g_h    [NTOK*DD];
__device__ float  g_tein [BB*DD];
__device__ float  g_teh  [BB*DFF];
__device__ float  g_te   [BB*DD];
__device__ float  g_cos  [TT*32];
__device__ float  g_sin  [TT*32];
__device__ __half g_hnh  [NTOK*DD];     // LN out (half); also gathered head input
__device__ __half g_qkvh [NTOK*3*DD];
__device__ __half g_oh   [NTOK*DD];
__device__ __half g_ffnh [NTOK*DFF];
// transposed half weights  [L][N][K] K-major
__device__ __half g_qkvw [LL*DD*3*DD];
__device__ __half g_projw[LL*DD*DD];
__device__ __half g_fc1w [LL*DD*DFF];
__device__ __half g_fc2w [LL*DFF*DD];
__device__ __half g_headw[NHPAD*DD];    // head weight [1152][1024], zero-padded

__device__ __forceinline__ float gelu_exact(float x) {
    return 0.5f * x * (1.0f + erff(x * 0.70710678118654752440f));
}
// p = 2^f for two packed args (MUFU f16x2)
__device__ __forceinline__ uint32_t exp2h2(float f0, float f1) {
    __half2 h = __floats2half2_rn(f0, f1);
    __half2 p = h2exp2(h);
    return *reinterpret_cast<uint32_t*>(&p);
}

// fp16 mma: C(16x8,f32) += A(16x16,f16 row) * B(16x8,f16 col)
__device__ __forceinline__ void mma_f16(float* c, const uint32_t* a, const uint32_t* b) {
    asm volatile(
        "mma.sync.aligned.m16n8k16.row.col.f32.f16.f16.f32 "
        "{%0,%1,%2,%3}, {%4,%5,%6,%7}, {%8,%9}, {%0,%1,%2,%3};"
        : "+f"(c[0]), "+f"(c[1]), "+f"(c[2]), "+f"(c[3])
        : "r"(a[0]), "r"(a[1]), "r"(a[2]), "r"(a[3]), "r"(b[0]), "r"(b[1]));
}
__device__ __forceinline__ void cp_async16(uint32_t saddr, const void* gptr) {
    asm volatile("cp.async.cg.shared.global [%0], [%1], 16;\n" :: "r"(saddr), "l"(gptr));
}
#define LDSM_X4(r0,r1,r2,r3,a) \
    asm volatile("ldmatrix.sync.aligned.m8n8.x4.shared.b16 {%0,%1,%2,%3}, [%4];" \
        : "=r"(r0),"=r"(r1),"=r"(r2),"=r"(r3) : "r"(a))
#define LDSM_X4T(r0,r1,r2,r3,a) \
    asm volatile("ldmatrix.sync.aligned.m8n8.x4.trans.shared.b16 {%0,%1,%2,%3}, [%4];" \
        : "=r"(r0),"=r"(r1),"=r"(r2),"=r"(r3) : "r"(a))

// =======================================================================
// prep_kernel v2: weight transposes (fp32 [K,N] -> half [N,K]) with
// coalesced half2 stores. Tile = 64 K x 32 N, block (32,8).
// Read: 8 x 128B rows. Write: 32 rows of 128B (one half2 per thread).
// Segments (block counts): qkv 18432 | proj 6144 | fc1 24576 | fc2 24576
//                          | head 576 | rope 64
// =======================================================================
#define P2_QKV   18432
#define P2_PROJ  (P2_QKV + 6144)
#define P2_FC1   (P2_PROJ + 24576)
#define P2_FC2   (P2_FC1 + 24576)
#define P2_HEAD  (P2_FC2 + 576)
#define P2_TOTAL (P2_HEAD + 64)

__global__ void prep_kernel(
        const float* __restrict__ qkv_w, const float* __restrict__ proj_w,
        const float* __restrict__ fc1_w, const float* __restrict__ fc2_w,
        const float* __restrict__ head_w,
        __half* __restrict__ qkvw, __half* __restrict__ projw,
        __half* __restrict__ fc1w, __half* __restrict__ fc2w,
        __half* __restrict__ headw,
        float* __restrict__ cosT, float* __restrict__ sinT) {
    __shared__ float tile[64][33];
    int bid = blockIdx.x;
    int tx = threadIdx.x, ty = threadIdx.y;

    if (bid >= P2_HEAD) {                 // rope tables
        int idx = (bid - P2_HEAD) * 256 + ty*32 + tx;
        int t = idx >> 5, j = idx & 31;
        float freq = expf(-(float)j * (logf(10000.0f) / 32.0f));
        float ang = (float)t * freq;
        cosT[idx] = cosf(ang);
        sinT[idx] = sinf(ang);
        return;
    }

    const float* src; __half* dst; int K, N, n0, k0;
    bool head = false;
    if (bid < P2_QKV) {                   // KT=16, NT=96
        int r = bid, l = r / 1536; r %= 1536;
        K = DD; N = 3*DD;
        k0 = (r / 96) * 64; n0 = (r % 96) * 32;
        src = qkv_w + (size_t)l*K*N; dst = qkvw + (size_t)l*K*N;
    } else if (bid < P2_PROJ) {           // KT=16, NT=32
        int r = bid - P2_QKV, l = r / 512; r %= 512;
        K = DD; N = DD;
        k0 = (r / 32) * 64; n0 = (r % 32) * 32;
        src = proj_w + (size_t)l*K*N; dst = projw + (size_t)l*K*N;
    } else if (bid < P2_FC1) {            // KT=16, NT=128
        int r = bid - P2_PROJ, l = r / 2048; r %= 2048;
        K = DD; N = DFF;
        k0 = (r / 128) * 64; n0 = (r % 128) * 32;
        src = fc1_w + (size_t)l*K*N; dst = fc1w + (size_t)l*K*N;
    } else if (bid < P2_FC2) {            // KT=64, NT=32
        int r = bid - P2_FC1, l = r / 2048; r %= 2048;
        K = DFF; N = DD;
        k0 = (r / 32) * 64; n0 = (r % 32) * 32;
        src = fc2_w + (size_t)l*K*N; dst = fc2w + (size_t)l*K*N;
    } else {                              // head: KT=16, NT=36; src [1024][1025]
        int r = bid - P2_FC2;
        K = DD; N = V0;                   // src stride V0; dst stride DD
        k0 = (r / 36) * 64; n0 = (r % 36) * 32;
        src = head_w; dst = headw;
        head = true;
    }

    if (head) {
        #pragma unroll
        for (int j = 0; j < 8; j++) {
            int kk = ty + j*8;
            int n = n0 + tx;
            tile[kk][tx] = (n < V0) ? src[(size_t)(k0+kk)*V0 + n] : 0.f;
        }
        __syncthreads();
        #pragma unroll
        for (int i = 0; i < 4; i++) {
            int nn = ty*4 + i;
            __half2 hv = __floats2half2_rn(tile[2*tx][nn], tile[2*tx+1][nn]);
            *reinterpret_cast<__half2*>(dst + (size_t)(n0+nn)*DD + k0 + 2*tx) = hv;
        }
        return;
    }

    #pragma unroll
    for (int j = 0; j < 8; j++) {
        int kk = ty + j*8;
        tile[kk][tx] = src[(size_t)(k0+kk)*N + n0+tx];
    }
    __syncthreads();
    #pragma unroll
    for (int i = 0; i < 4; i++) {
        int nn = ty*4 + i;
        __half2 hv = __floats2half2_rn(tile[2*tx][nn], tile[2*tx+1][nn]);
        *reinterpret_cast<__half2*>(dst + (size_t)(n0+nn)*K + k0 + 2*tx) = hv;
    }
}

// ---------------- time embedding ----------------
__global__ void te_in_kernel(const int* __restrict__ t, float* __restrict__ out) {
    int b = blockIdx.x;
    int j = threadIdx.x;
    float tv = (float)t[b];
    float e  = expf((float)j * (-logf(10000.0f) / 511.0f));
    float v  = tv * e;
    out[b*DD + j]       = sinf(v);
    out[b*DD + 512 + j] = cosf(v);
}

template<int EPI>  // 0 = bias only, 2 = gelu(bias+)
__global__ void tgemm_kernel(const float* __restrict__ A, const float* __restrict__ Bw,
                             const float* __restrict__ bias, float* __restrict__ C,
                             int K, int N) {
    int n = blockIdx.x * blockDim.x + threadIdx.x;
    if (n >= N) return;
    float acc[16];
    #pragma unroll
    for (int m = 0; m < 16; m++) acc[m] = 0.f;
    for (int k = 0; k < K; k++) {
        float bv = Bw[(size_t)k*N + n];
        #pragma unroll
        for (int m = 0; m < 16; m++) acc[m] += A[m*K + k] * bv;
    }
    float bs = bias[n];
    #pragma unroll
    for (int m = 0; m < 16; m++) {
        float v = acc[m] + bs;
        if (EPI == 2) v = gelu_exact(v);
        C[(size_t)m*N + n] = v;
    }
}

// ---------------- embedding + layer-0 LN1 (fused) ----------------
__global__ void __launch_bounds__(256) embed_ln_kernel(
        const int* __restrict__ x, const int* __restrict__ level,
        const float* __restrict__ tok_emb, const float* __restrict__ level_emb,
        const float* __restrict__ te, float* __restrict__ h,
        const float* __restrict__ g, const float* __restrict__ b,
        __half* __restrict__ y) {
    int n = blockIdx.x;
    int bidx = n >> 9;
    int lvl = level[0];
    int tid = threadIdx.x;
    const float4* tk = (const float4*)(tok_emb + (size_t)x[n]*DD);
    const float4* le = (const float4*)(level_emb + (size_t)lvl*DD);
    const float4* tv = (const float4*)(te + (size_t)bidx*DD);
    float4 a = tk[tid], c = le[tid], d = tv[tid];
    float4 v = make_float4(a.x+c.x+d.x, a.y+c.y+d.y, a.z+c.z+d.z, a.w+c.w+d.w);
    ((float4*)(h + (size_t)n*DD))[tid] = v;

    float s  = v.x + v.y + v.z + v.w;
    float ss = v.x*v.x + v.y*v.y + v.z*v.z + v.w*v.w;
    __shared__ float sh1[8], sh2[8], shm[2];
    int lane = tid & 31, w = tid >> 5;
    #pragma unroll
    for (int o = 16; o > 0; o >>= 1) {
        s  += __shfl_xor_sync(0xffffffffu, s,  o);
        ss += __shfl_xor_sync(0xffffffffu, ss, o);
    }
    if (lane == 0) { sh1[w] = s; sh2[w] = ss; }
    __syncthreads();
    if (tid == 0) {
        float ts = 0.f, tss = 0.f;
        #pragma unroll
        for (int i = 0; i < 8; i++) { ts += sh1[i]; tss += sh2[i]; }
        float mean = ts * (1.0f/DD);
        float var  = tss * (1.0f/DD) - mean*mean;
        shm[0] = mean;
        shm[1] = rsqrtf(var + 1e-5f);
    }
    __syncthreads();
    float mean = shm[0], rs = shm[1];
    float4 gg = ((const float4*)g)[tid];
    float4 bb = ((const float4*)b)[tid];
    __half2* y2 = (__half2*)(y + (size_t)n*DD);
    y2[tid*2+0] = __floats2half2_rn((v.x-mean)*rs*gg.x + bb.x, (v.y-mean)*rs*gg.y + bb.y);
    y2[tid*2+1] = __floats2half2_rn((v.z-mean)*rs*gg.z + bb.z, (v.w-mean)*rs*gg.w + bb.w);
}

// ---------------- layernorm -> half out ----------------
__global__ void __launch_bounds__(256) layernorm_kernel(
        const float* __restrict__ x, const float* __restrict__ g,
        const float* __restrict__ b, __half* __restrict__ y) {
    size_t row = blockIdx.x;
    int tid = threadIdx.x;
    const float4* xr = (const float4*)(x + row*DD);
    float4 v = xr[tid];
    float s  = v.x + v.y + v.z + v.w;
    float ss = v.x*v.x + v.y*v.y + v.z*v.z + v.w*v.w;
    __shared__ float sh1[8], sh2[8], shm[2];
    int lane = tid & 31, w = tid >> 5;
    #pragma unroll
    for (int o = 16; o > 0; o >>= 1) {
        s  += __shfl_xor_sync(0xffffffffu, s,  o);
        ss += __shfl_xor_sync(0xffffffffu, ss, o);
    }
    if (lane == 0) { sh1[w] = s; sh2[w] = ss; }
    __syncthreads();
    if (tid == 0) {
        float ts = 0.f, tss = 0.f;
        #pragma unroll
        for (int i = 0; i < 8; i++) { ts += sh1[i]; tss += sh2[i]; }
        float mean = ts * (1.0f/DD);
        float var  = tss * (1.0f/DD) - mean*mean;
        shm[0] = mean;
        shm[1] = rsqrtf(var + 1e-5f);
    }
    __syncthreads();
    float mean = shm[0], rs = shm[1];
    float4 gg = ((const float4*)g)[tid];
    float4 bb = ((const float4*)b)[tid];
    __half2* y2 = (__half2*)(y + row*DD);
    y2[tid*2+0] = __floats2half2_rn((v.x-mean)*rs*gg.x + bb.x, (v.y-mean)*rs*gg.y + bb.y);
    y2[tid*2+1] = __floats2half2_rn((v.z-mean)*rs*gg.z + bb.z, (v.w-mean)*rs*gg.w + bb.w);
}

// ---------------- final layernorm + gather (t=1..511) -> half, padded ----
__global__ void __launch_bounds__(256) lnf_gather_kernel(
        const float* __restrict__ x, const float* __restrict__ g,
        const float* __restrict__ b, __half* __restrict__ y) {
    int m = blockIdx.x;          // 0..8191
    int tid = threadIdx.x;
    __half2* y2 = (__half2*)(y + (size_t)m*DD);
    if (m >= NHEADROWS) {
        __half2 z = __floats2half2_rn(0.f, 0.f);
        y2[tid*2+0] = z; y2[tid*2+1] = z;
        return;
    }
    int bb_ = m / TOUT, tt_ = m % TOUT + 1;
    size_t row = (size_t)(bb_*TT + tt_);
    const float4* xr = (const float4*)(x + row*DD);
    float4 v = xr[tid];
    float s  = v.x + v.y + v.z + v.w;
    float ss = v.x*v.x + v.y*v.y + v.z*v.z + v.w*v.w;
    __shared__ float sh1[8], sh2[8], shm[2];
    int lane = tid & 31, w = tid >> 5;
    #pragma unroll
    for (int o = 16; o > 0; o >>= 1) {
        s  += __shfl_xor_sync(0xffffffffu, s,  o);
        ss += __shfl_xor_sync(0xffffffffu, ss, o);
    }
    if (lane == 0) { sh1[w] = s; sh2[w] = ss; }
    __syncthreads();
    if (tid == 0) {
        float ts = 0.f, tss = 0.f;
        #pragma unroll
        for (int i = 0; i < 8; i++) { ts += sh1[i]; tss += sh2[i]; }
        float mean = ts * (1.0f/DD);
        float var  = tss * (1.0f/DD) - mean*mean;
        shm[0] = mean;
        shm[1] = rsqrtf(var + 1e-5f);
    }
    __syncthreads();
    float mean = shm[0], rs = shm[1];
    float4 gg = ((const float4*)g)[tid];
    float4 bb = ((const float4*)b)[tid];
    y2[tid*2+0] = __floats2half2_rn((v.x-mean)*rs*gg.x + bb.x, (v.y-mean)*rs*gg.y + bb.y);
    y2[tid*2+1] = __floats2half2_rn((v.z-mean)*rs*gg.z + bb.z, (v.w-mean)*rs*gg.w + bb.w);
}

// =======================================================================
// fp16 GEMM: C = A[M,K] @ BT[N,K]^T.  M%128==0, N%128==0, K%32==0.
// 128x128x32 tile, 3-buffer cp.async ring, 2 CTAs/SM.
// EPI: 0 = head (float out, stride NC, bounds), 1 = +residual(float out),
//      2 = gelu(half out), 3 = rope-qkv(half out, q*0.125)
// =======================================================================
#define HPITCH 40
#define HSTAGE 20480
#define HG_SMEM (3*HSTAGE)        // 61440 -> two CTAs fit per SM

template<int EPI>
__global__ void __launch_bounds__(256, 2) hgemm_kernel(
        const __half* __restrict__ A, const __half* __restrict__ BT,
        const float* __restrict__ Cres, void* __restrict__ Cv,
        int N, int K,
        const float* __restrict__ cosT, const float* __restrict__ sinT,
        int NC) {
    extern __shared__ __align__(16) char smem[];
    uint32_t sb = (uint32_t)__cvta_generic_to_shared(smem);
    int tid = threadIdx.x;
    int bn0 = blockIdx.x * 128, bm0 = blockIdx.y * 128;
    int wid = tid >> 5, lane = tid & 31;
    int wm = (wid & 3) * 32;
    int wn = (wid >> 2) * 64;
    int mc = lane >> 2;
    int kq2 = (lane & 3) * 2;

    float c[2][8][4];
    #pragma unroll
    for (int mt = 0; mt < 2; mt++)
        #pragma unroll
        for (int nt = 0; nt < 8; nt++)
            #pragma unroll
            for (int i = 0; i < 4; i++) c[mt][nt][i] = 0.f;

    int NIT = K >> 5;

    int a_r = lane & 15, a_c = (lane >> 4) * 8;
    int b_r = ((lane >> 4) << 3) + (lane & 7), b_c = ((lane >> 3) & 1) * 8;
    uint32_t aoff[2][2], boff[2][4];
    #pragma unroll
    for (int ks = 0; ks < 2; ks++) {
        #pragma unroll
        for (int mt = 0; mt < 2; mt++)
            aoff[ks][mt] = (uint32_t)((wm + mt*16 + a_r)*80 + (ks*16 + a_c)*2);
        #pragma unroll
        for (int p = 0; p < 4; p++)
            boff[ks][p] = (uint32_t)(10240 + (wn + p*16 + b_r)*80 + (ks*16 + b_c)*2);
    }

    auto load_stage = [&](int s, int buf) {
        int k0 = s << 5;
        uint32_t abase = sb + buf*HSTAGE;
        uint32_t bbase = abase + 10240;
        #pragma unroll
        for (int j = 0; j < 2; j++) {
            int ch = (tid << 1) + j;
            int row = ch >> 2, q = ch & 3;
            cp_async16(abase + row*80 + q*16, A + (size_t)(bm0 + row)*K + k0 + q*8);
        }
        #pragma unroll
        for (int j = 0; j < 2; j++) {
            int ch = (tid << 1) + j;
            int row = ch >> 2, q = ch & 3;
            cp_async16(bbase + row*80 + q*16, BT + (size_t)(bn0 + row)*K + k0 + q*8);
        }
    };

    load_stage(0, 0); asm volatile("cp.async.commit_group;");
    load_stage(1, 1); asm volatile("cp.async.commit_group;");

    int bufM = 0, bufL = 2;
    for (int it = 0; it < NIT; it++) {
        asm volatile("cp.async.wait_group 1;");
        __syncthreads();
        // buffer bufL was consumed in iteration it-1; every warp past the
        // barrier above has finished that MMA phase -> safe to refill now.
        if (it + 2 < NIT) load_stage(it + 2, bufL);
        asm volatile("cp.async.commit_group;");

        uint32_t stage = sb + bufM*HSTAGE;
        #pragma unroll
        for (int ks = 0; ks < 2; ks++) {
            uint32_t af[2][4], bf[8][2];
            LDSM_X4(af[0][0], af[0][1], af[0][2], af[0][3], stage + aoff[ks][0]);
            LDSM_X4(af[1][0], af[1][1], af[1][2], af[1][3], stage + aoff[ks][1]);
            #pragma unroll
            for (int p = 0; p < 4; p++)
                LDSM_X4(bf[2*p][0], bf[2*p][1], bf[2*p+1][0], bf[2*p+1][1],
                        stage + boff[ks][p]);
            #pragma unroll
            for (int mt = 0; mt < 2; mt++)
                #pragma unroll
                for (int nt = 0; nt < 8; nt++)
                    mma_f16(c[mt][nt], af[mt], bf[nt]);
        }
        bufL = bufM;
        bufM = (bufM == 2) ? 0 : bufM + 1;
    }

    // ---------------- epilogue ----------------
    #pragma unroll
    for (int mt = 0; mt < 2; mt++) {
        int r0 = bm0 + wm + mt*16 + mc;
        #pragma unroll
        for (int nt = 0; nt < 8; nt++) {
            int col = bn0 + wn + nt*8 + kq2;
            #pragma unroll
            for (int half_ = 0; half_ < 2; half_++) {
                int r = r0 + half_*8;
                float v0 = c[mt][nt][half_*2 + 0];
                float v1 = c[mt][nt][half_*2 + 1];
                if (EPI == 0) {
                    float* C = (float*)Cv;
                    if (r < NHEADROWS) {
                        if (col < NC)     C[(size_t)r*NC + col]     = v0;
                        if (col + 1 < NC) C[(size_t)r*NC + col + 1] = v1;
                    }
                } else if (EPI == 1) {
                    float* C = (float*)Cv;
                    const float2 res = *reinterpret_cast<const float2*>(Cres + (size_t)r*N + col);
                    v0 += res.x; v1 += res.y;
                    *reinterpret_cast<float2*>(C + (size_t)r*N + col) = make_float2(v0, v1);
                } else if (EPI == 2) {
                    __half* C = (__half*)Cv;
                    __half2 hv = __halves2half2(__float2half_rn(gelu_exact(v0)),
                                                __float2half_rn(gelu_exact(v1)));
                    *reinterpret_cast<__half2*>(C + (size_t)r*N + col) = hv;
                } else {   // EPI 3: rope on q/k pairs, q pre-scaled by 1/8 (exact)
                    __half* C = (__half*)Cv;
                    if (col < 2*DD) {
                        int j = (col & 63) >> 1;
                        int t = r & (TT-1);
                        float cc = cosT[t*32 + j], ssn = sinT[t*32 + j];
                        float x1 = v0, x2 = v1;
                        v0 = x1*cc - x2*ssn;
                        v1 = x1*ssn + x2*cc;
                        if (col < DD) { v0 *= 0.125f; v1 *= 0.125f; }
                    }
                    __half2 hv = __halves2half2(__float2half_rn(v0), __float2half_rn(v1));
                    *reinterpret_cast<__half2*>(C + (size_t)r*N + col) = hv;
                }
            }
        }
    }
}

// =======================================================================
// Flash attention: one block = 128 q rows x one (b,h). 8 warps (16 q each),
// online softmax in exp2/f16x2, row-sum via MMA-with-ones.
// Q fragments reloaded from smem per K-tile (register reduction -> 2 CTAs/SM
// without spills). Q pre-scaled by 1/sqrt(64). O written as half.
// =======================================================================
#define FA_SMEM (128*144 + 2*64*144 + 2*64*144)   // 55296
#define LOG2E 1.4426950408889634f

__global__ void __launch_bounds__(256, 2) flash_attn_kernel(
        const __half* __restrict__ qkv, __half* __restrict__ o) {
    extern __shared__ __align__(16) char fsmem[];
    uint32_t sQ = (uint32_t)__cvta_generic_to_shared(fsmem);
    uint32_t sK = sQ + 128*144;
    uint32_t sV = sK + 2*64*144;
    int bh = blockIdx.y;
    int b = bh >> 4, h = bh & 15;
    int q0 = blockIdx.x * 128;
    int tid = threadIdx.x, wid = tid >> 5, lane = tid & 31;
    int mc = lane >> 2, kq2 = (lane & 3) * 2;

    auto load_kv = [&](int kc, int buf) {
        #pragma unroll
        for (int j = 0; j < 2; j++) {
            int ch = tid + j*256;
            int row = ch >> 3, seg = ch & 7;
            size_t base = (size_t)(b*TT + kc*64 + row)*3*DD + h*HDIM + seg*8;
            cp_async16(sK + buf*9216 + row*144 + seg*16, qkv + base + DD);
            cp_async16(sV + buf*9216 + row*144 + seg*16, qkv + base + 2*DD);
        }
    };

    #pragma unroll
    for (int j = 0; j < 4; j++) {
        int ch = tid + j*256;
        int row = ch >> 3, seg = ch & 7;
        cp_async16(sQ + row*144 + seg*16,
                   qkv + (size_t)(b*TT + q0 + row)*3*DD + h*HDIM + seg*8);
    }
    asm volatile("cp.async.commit_group;");
    load_kv(0, 0); asm volatile("cp.async.commit_group;");
    load_kv(1, 1); asm volatile("cp.async.commit_group;");

    asm volatile("cp.async.wait_group 2;");
    __syncthreads();

    // per-lane Q ldmatrix base (fragments reloaded each K-tile; Q smem is
    // never overwritten, so no extra sync needed)
    uint32_t qb = sQ + (uint32_t)((wid*16 + (lane & 15))*144 + ((lane >> 4)*8)*2);

    uint32_t kRow = (uint32_t)(((lane >> 4) << 3) + (lane & 7));
    uint32_t kCol = (uint32_t)(((lane >> 3) & 1) * 8);
    uint32_t vRow = (uint32_t)(lane & 15);
    uint32_t vCol = (uint32_t)((lane >> 4) * 8);

    const uint32_t ONES2[2] = {0x3C003C00u, 0x3C003C00u};

    float m0 = -1e30f, m1 = -1e30f;
    float lc[4] = {0.f, 0.f, 0.f, 0.f};
    float oa[8][4];
    #pragma unroll
    for (int nt = 0; nt < 8; nt++)
        #pragma unroll
        for (int i = 0; i < 4; i++) oa[nt][i] = 0.f;

    for (int kc = 0; kc < 8; kc++) {
        asm volatile("cp.async.wait_group 1;");
        __syncthreads();
        uint32_t kb = sK + (kc & 1)*9216;
        uint32_t vb = sV + (kc & 1)*9216;

        float s[8][4];
        #pragma unroll
        for (int nt = 0; nt < 8; nt++)
            #pragma unroll
            for (int i = 0; i < 4; i++) s[nt][i] = 0.f;
        #pragma unroll
        for (int ks = 0; ks < 4; ks++) {
            uint32_t qf[4];
            LDSM_X4(qf[0], qf[1], qf[2], qf[3], qb + ks*32);
            uint32_t bf[8][2];
            #pragma unroll
            for (int p = 0; p < 4; p++)
                LDSM_X4(bf[2*p][0], bf[2*p][1], bf[2*p+1][0], bf[2*p+1][1],
                        kb + (p*16 + kRow)*144 + (ks*16 + kCol)*2);
            #pragma unroll
            for (int nt = 0; nt < 8; nt++) mma_f16(s[nt], qf, bf[nt]);
        }

        float mx0 = -1e30f, mx1 = -1e30f;
        #pragma unroll
        for (int nt = 0; nt < 8; nt++) {
            mx0 = fmaxf(mx0, fmaxf(s[nt][0], s[nt][1]));
            mx1 = fmaxf(mx1, fmaxf(s[nt][2], s[nt][3]));
        }
        mx0 = fmaxf(mx0, __shfl_xor_sync(0xffffffffu, mx0, 1));
        mx0 = fmaxf(mx0, __shfl_xor_sync(0xffffffffu, mx0, 2));
        mx1 = fmaxf(mx1, __shfl_xor_sync(0xffffffffu, mx1, 1));
        mx1 = fmaxf(mx1, __shfl_xor_sync(0xffffffffu, mx1, 2));
        float m0n = fmaxf(m0, mx0), m1n = fmaxf(m1, mx1);
        float a0 = __expf(m0 - m0n), a1 = __expf(m1 - m1n);
        float c0 = m0n * LOG2E, c1 = m1n * LOG2E;

        uint32_t pf[4][4];
        #pragma unroll
        for (int tp = 0; tp < 4; tp++) {
            pf[tp][0] = exp2h2(s[2*tp][0]  *LOG2E - c0, s[2*tp][1]  *LOG2E - c0);
            pf[tp][1] = exp2h2(s[2*tp][2]  *LOG2E - c1, s[2*tp][3]  *LOG2E - c1);
            pf[tp][2] = exp2h2(s[2*tp+1][0]*LOG2E - c0, s[2*tp+1][1]*LOG2E - c0);
            pf[tp][3] = exp2h2(s[2*tp+1][2]*LOG2E - c1, s[2*tp+1][3]*LOG2E - c1);
        }
        m0 = m0n; m1 = m1n;
        lc[0] *= a0; lc[1] *= a0; lc[2] *= a1; lc[3] *= a1;
        #pragma unroll
        for (int nt = 0; nt < 8; nt++) {
            oa[nt][0] *= a0; oa[nt][1] *= a0;
            oa[nt][2] *= a1; oa[nt][3] *= a1;
        }
        #pragma unroll
        for (int kt = 0; kt < 4; kt++) mma_f16(lc, pf[kt], ONES2);

        #pragma unroll
        for (int kt = 0; kt < 4; kt++) {
            #pragma unroll
            for (int p = 0; p < 4; p++) {
                uint32_t v0, v1, v2, v3;
                LDSM_X4T(v0, v1, v2, v3,
                         vb + (kt*16 + vRow)*144 + (p*16 + vCol)*2);
                uint32_t bv0[2] = {v0, v1}, bv1[2] = {v2, v3};
                mma_f16(oa[2*p],   pf[kt], bv0);
                mma_f16(oa[2*p+1], pf[kt], bv1);
            }
        }

        __syncthreads();
        if (kc + 2 < 8) load_kv(kc + 2, kc & 1);
        asm volatile("cp.async.commit_group;");
    }

    float i0 = 1.f / lc[0], i1 = 1.f / lc[2];
    int r0 = b*TT + q0 + wid*16 + mc;
    #pragma unroll
    for (int nt = 0; nt < 8; nt++) {
        int col = h*HDIM + nt*8 + kq2;
        *reinterpret_cast<__half2*>(o + (size_t)r0*DD + col) =
            __halves2half2(__float2half_rn(oa[nt][0]*i0), __float2half_rn(oa[nt][1]*i0));
        *reinterpret_cast<__half2*>(o + (size_t)(r0+8)*DD + col) =
            __halves2half2(__float2half_rn(oa[nt][2]*i1), __float2half_rn(oa[nt][3]*i1));
    }
}

// ---------------- host side ----------------
static inline int cdiv(int a, int b) { return (a + b - 1) / b; }

extern "C" void kernel_launch(void* const* d_in, const int* in_sizes, int n_in,
                              void* d_out, int out_size) {
    const int*   x         = (const int*)  d_in[0];
    const int*   t         = (const int*)  d_in[1];
    const int*   level     = (const int*)  d_in[2];
    const float* tok_emb   = (const float*)d_in[3];
    const float* level_emb = (const float*)d_in[4];
    const float* time_w1   = (const float*)d_in[5];
    const float* time_b1   = (const float*)d_in[6];
    const float* time_w2   = (const float*)d_in[7];
    const float* time_b2   = (const float*)d_in[8];
    const float* ln1_g     = (const float*)d_in[9];
    const float* ln1_b     = (const float*)d_in[10];
    const float* qkv_w     = (const float*)d_in[11];
    const float* proj_w    = (const float*)d_in[12];
    const float* ln2_g     = (const float*)d_in[13];
    const float* ln2_b     = (const float*)d_in[14];
    const float* fc1_w     = (const float*)d_in[15];
    const float* fc2_w     = (const float*)d_in[16];
    const float* lnf_g     = (const float*)d_in[17];
    const float* lnf_b     = (const float*)d_in[18];
    const float* head0_w   = (const float*)d_in[19];

    float  *ph, *ptein, *pteh, *pte, *pcos, *psin;
    __half *phnh, *pqkvh, *poh, *pffnh;
    __half *pqkvw, *pprojw, *pfc1w, *pfc2w, *pheadw;
    cudaGetSymbolAddress((void**)&ph,    g_h);
    cudaGetSymbolAddress((void**)&ptein, g_tein);
    cudaGetSymbolAddress((void**)&pteh,  g_teh);
    cudaGetSymbolAddress((void**)&pte,   g_te);
    cudaGetSymbolAddress((void**)&pcos,  g_cos);
    cudaGetSymbolAddress((void**)&psin,  g_sin);
    cudaGetSymbolAddress((void**)&phnh,  g_hnh);
    cudaGetSymbolAddress((void**)&pqkvh, g_qkvh);
    cudaGetSymbolAddress((void**)&poh,   g_oh);
    cudaGetSymbolAddress((void**)&pffnh, g_ffnh);
    cudaGetSymbolAddress((void**)&pqkvw, g_qkvw);
    cudaGetSymbolAddress((void**)&pprojw,g_projw);
    cudaGetSymbolAddress((void**)&pfc1w, g_fc1w);
    cudaGetSymbolAddress((void**)&pfc2w, g_fc2w);
    cudaGetSymbolAddress((void**)&pheadw,g_headw);

    cudaFuncSetAttribute(hgemm_kernel<0>, cudaFuncAttributeMaxDynamicSharedMemorySize, HG_SMEM);
    cudaFuncSetAttribute(hgemm_kernel<1>, cudaFuncAttributeMaxDynamicSharedMemorySize, HG_SMEM);
    cudaFuncSetAttribute(hgemm_kernel<2>, cudaFuncAttributeMaxDynamicSharedMemorySize, HG_SMEM);
    cudaFuncSetAttribute(hgemm_kernel<3>, cudaFuncAttributeMaxDynamicSharedMemorySize, HG_SMEM);
    cudaFuncSetAttribute(flash_attn_kernel, cudaFuncAttributeMaxDynamicSharedMemorySize, FA_SMEM);

    dim3 blk(256);
    dim3 tb(32, 8);

    te_in_kernel<<<BB, 512>>>(t, ptein);
    tgemm_kernel<2><<<cdiv(DFF,128), 128>>>(ptein, time_w1, time_b1, pteh, DD, DFF);
    tgemm_kernel<0><<<cdiv(DD,128), 128>>>(pteh, time_w2, time_b2, pte, DFF, DD);
    prep_kernel<<<P2_TOTAL, tb>>>(qkv_w, proj_w, fc1_w, fc2_w, head0_w,
                                  pqkvw, pprojw, pfc1w, pfc2w, pheadw,
                                  pcos, psin);
    embed_ln_kernel<<<NTOK, 256>>>(x, level, tok_emb, level_emb, pte, ph,
                                   ln1_g, ln1_b, phnh);

    for (int i = 0; i < LL; i++) {
        hgemm_kernel<3><<<dim3(3*DD/128, NTOK/128), blk, HG_SMEM>>>(
            phnh, pqkvw + (size_t)i*DD*3*DD, nullptr, pqkvh, 3*DD, DD, pcos, psin, 0);

        flash_attn_kernel<<<dim3(TT/128, BB*HH), 256, FA_SMEM>>>(pqkvh, poh);

        hgemm_kernel<1><<<dim3(DD/128, NTOK/128), blk, HG_SMEM>>>(
            poh, pprojw + (size_t)i*DD*DD, ph, ph, DD, DD, pcos, psin, 0);

        layernorm_kernel<<<NTOK, 256>>>(ph, ln2_g + i*DD, ln2_b + i*DD, phnh);

        hgemm_kernel<2><<<dim3(DFF/128, NTOK/128), blk, HG_SMEM>>>(
            phnh, pfc1w + (size_t)i*DD*DFF, nullptr, pffnh, DFF, DD, pcos, psin, 0);

        hgemm_kernel<1><<<dim3(DD/128, NTOK/128), blk, HG_SMEM>>>(
            pffnh, pfc2w + (size_t)i*DFF*DD, ph, ph, DD, DFF, pcos, psin, 0);

        if (i + 1 < LL)
            layernorm_kernel<<<NTOK, 256>>>(ph, ln1_g + (i+1)*DD, ln1_b + (i+1)*DD, phnh);
    }

    // final LN fused with gather (zero-padded to 8192 rows), fp16 head GEMM
    lnf_gather_kernel<<<NTOK, 256>>>(ph, lnf_g, lnf_b, phnh);
    hgemm_kernel<0><<<dim3(NHPAD/128, NTOK/128), blk, HG_SMEM>>>(
        phnh, pheadw, nullptr, (float*)d_out, NHPAD, DD, pcos, psin, V0);
}

// round 17
// speedup vs baseline: 1.2471x; 1.2471x over previous
#include <cuda_runtime.h>
#include <cuda_fp16.h>
#include <math.h>
#include <stdint.h>

// ---------------- problem constants ----------------
#define BB   16
#define TT   512
#define NTOK (BB*TT)        // 8192
#define DD   1024
#define HH   16
#define HDIM 64
#define LL   12
#define DFF  4096
#define V0   1025
#define TOUT 511
#define NHEADROWS (BB*TOUT) // 8176
#define NHPAD 1152          // head N padded to 9*128

// ---------------- scratch (device globals; no allocation allowed) -------
__device__ float  g_h    [NTOK*DD];
__device__ float  g_tein [BB*DD];
__device__ float  g_teh  [BB*DFF];
__device__ float  g_te   [BB*DD];
__device__ float  g_cos  [TT*32];
__device__ float  g_sin  [TT*32];
__device__ __half g_hnh  [NTOK*DD];     // LN out (half); also gathered head input
__device__ __half g_qkvh [NTOK*3*DD];
__device__ __half g_oh   [NTOK*DD];
__device__ __half g_ffnh [NTOK*DFF];
// transposed half weights  [L][N][K] K-major
__device__ __half g_qkvw [LL*DD*3*DD];
__device__ __half g_projw[LL*DD*DD];
__device__ __half g_fc1w [LL*DD*DFF];
__device__ __half g_fc2w [LL*DFF*DD];
__device__ __half g_headw[NHPAD*DD];    // head weight [1152][1024], zero-padded

__device__ __forceinline__ float gelu_exact(float x) {
    return 0.5f * x * (1.0f + erff(x * 0.70710678118654752440f));
}
// p = 2^f for two packed args (MUFU f16x2)
__device__ __forceinline__ uint32_t exp2h2(float f0, float f1) {
    __half2 h = __floats2half2_rn(f0, f1);
    __half2 p = h2exp2(h);
    return *reinterpret_cast<uint32_t*>(&p);
}

// fp16 mma: C(16x8,f32) += A(16x16,f16 row) * B(16x8,f16 col)
__device__ __forceinline__ void mma_f16(float* c, const uint32_t* a, const uint32_t* b) {
    asm volatile(
        "mma.sync.aligned.m16n8k16.row.col.f32.f16.f16.f32 "
        "{%0,%1,%2,%3}, {%4,%5,%6,%7}, {%8,%9}, {%0,%1,%2,%3};"
        : "+f"(c[0]), "+f"(c[1]), "+f"(c[2]), "+f"(c[3])
        : "r"(a[0]), "r"(a[1]), "r"(a[2]), "r"(a[3]), "r"(b[0]), "r"(b[1]));
}
__device__ __forceinline__ void cp_async16(uint32_t saddr, const void* gptr) {
    asm volatile("cp.async.cg.shared.global [%0], [%1], 16;\n" :: "r"(saddr), "l"(gptr));
}
#define LDSM_X4(r0,r1,r2,r3,a) \
    asm volatile("ldmatrix.sync.aligned.m8n8.x4.shared.b16 {%0,%1,%2,%3}, [%4];" \
        : "=r"(r0),"=r"(r1),"=r"(r2),"=r"(r3) : "r"(a))
#define LDSM_X4T(r0,r1,r2,r3,a) \
    asm volatile("ldmatrix.sync.aligned.m8n8.x4.trans.shared.b16 {%0,%1,%2,%3}, [%4];" \
        : "=r"(r0),"=r"(r1),"=r"(r2),"=r"(r3) : "r"(a))

// =======================================================================
// prep_kernel v2: weight transposes (fp32 [K,N] -> half [N,K]) with
// coalesced half2 stores. Tile = 64 K x 32 N, block (32,8).
// =======================================================================
#define P2_QKV   18432
#define P2_PROJ  (P2_QKV + 6144)
#define P2_FC1   (P2_PROJ + 24576)
#define P2_FC2   (P2_FC1 + 24576)
#define P2_HEAD  (P2_FC2 + 576)
#define P2_TOTAL (P2_HEAD + 64)

__global__ void prep_kernel(
        const float* __restrict__ qkv_w, const float* __restrict__ proj_w,
        const float* __restrict__ fc1_w, const float* __restrict__ fc2_w,
        const float* __restrict__ head_w,
        __half* __restrict__ qkvw, __half* __restrict__ projw,
        __half* __restrict__ fc1w, __half* __restrict__ fc2w,
        __half* __restrict__ headw,
        float* __restrict__ cosT, float* __restrict__ sinT) {
    __shared__ float tile[64][33];
    int bid = blockIdx.x;
    int tx = threadIdx.x, ty = threadIdx.y;

    if (bid >= P2_HEAD) {                 // rope tables
        int idx = (bid - P2_HEAD) * 256 + ty*32 + tx;
        int t = idx >> 5, j = idx & 31;
        float freq = expf(-(float)j * (logf(10000.0f) / 32.0f));
        float ang = (float)t * freq;
        cosT[idx] = cosf(ang);
        sinT[idx] = sinf(ang);
        return;
    }

    const float* src; __half* dst; int K, N, n0, k0;
    bool head = false;
    if (bid < P2_QKV) {
        int r = bid, l = r / 1536; r %= 1536;
        K = DD; N = 3*DD;
        k0 = (r / 96) * 64; n0 = (r % 96) * 32;
        src = qkv_w + (size_t)l*K*N; dst = qkvw + (size_t)l*K*N;
    } else if (bid < P2_PROJ) {
        int r = bid - P2_QKV, l = r / 512; r %= 512;
        K = DD; N = DD;
        k0 = (r / 32) * 64; n0 = (r % 32) * 32;
        src = proj_w + (size_t)l*K*N; dst = projw + (size_t)l*K*N;
    } else if (bid < P2_FC1) {
        int r = bid - P2_PROJ, l = r / 2048; r %= 2048;
        K = DD; N = DFF;
        k0 = (r / 128) * 64; n0 = (r % 128) * 32;
        src = fc1_w + (size_t)l*K*N; dst = fc1w + (size_t)l*K*N;
    } else if (bid < P2_FC2) {
        int r = bid - P2_FC1, l = r / 2048; r %= 2048;
        K = DFF; N = DD;
        k0 = (r / 32) * 64; n0 = (r % 32) * 32;
        src = fc2_w + (size_t)l*K*N; dst = fc2w + (size_t)l*K*N;
    } else {                              // head: [1024][1025] -> [1152][1024]
        int r = bid - P2_FC2;
        K = DD; N = V0;
        k0 = (r / 36) * 64; n0 = (r % 36) * 32;
        src = head_w; dst = headw;
        head = true;
    }

    if (head) {
        #pragma unroll
        for (int j = 0; j < 8; j++) {
            int kk = ty + j*8;
            int n = n0 + tx;
            tile[kk][tx] = (n < V0) ? src[(size_t)(k0+kk)*V0 + n] : 0.f;
        }
        __syncthreads();
        #pragma unroll
        for (int i = 0; i < 4; i++) {
            int nn = ty*4 + i;
            __half2 hv = __floats2half2_rn(tile[2*tx][nn], tile[2*tx+1][nn]);
            *reinterpret_cast<__half2*>(dst + (size_t)(n0+nn)*DD + k0 + 2*tx) = hv;
        }
        return;
    }

    #pragma unroll
    for (int j = 0; j < 8; j++) {
        int kk = ty + j*8;
        tile[kk][tx] = src[(size_t)(k0+kk)*N + n0+tx];
    }
    __syncthreads();
    #pragma unroll
    for (int i = 0; i < 4; i++) {
        int nn = ty*4 + i;
        __half2 hv = __floats2half2_rn(tile[2*tx][nn], tile[2*tx+1][nn]);
        *reinterpret_cast<__half2*>(dst + (size_t)(n0+nn)*K + k0 + 2*tx) = hv;
    }
}

// ---------------- time embedding ----------------
__global__ void te_in_kernel(const int* __restrict__ t, float* __restrict__ out) {
    int b = blockIdx.x;
    int j = threadIdx.x;
    float tv = (float)t[b];
    float e  = expf((float)j * (-logf(10000.0f) / 511.0f));
    float v  = tv * e;
    out[b*DD + j]       = sinf(v);
    out[b*DD + 512 + j] = cosf(v);
}

// small GEMM C[16,N] = A[16,K]@B[K,N] + bias (optional gelu), K-parallel.
// grid = N blocks of 128 threads; each block computes one output column.
template<int EPI>  // 0 = bias only, 2 = gelu(bias+)
__global__ void __launch_bounds__(128) tgemm_kernel(
        const float* __restrict__ A, const float* __restrict__ Bw,
        const float* __restrict__ bias, float* __restrict__ C,
        int K, int N) {
    int n = blockIdx.x;
    int tid = threadIdx.x;
    int lane = tid & 31, w = tid >> 5;
    float acc[16];
    #pragma unroll
    for (int m = 0; m < 16; m++) acc[m] = 0.f;
    for (int k = tid; k < K; k += 128) {
        float bv = Bw[(size_t)k*N + n];
        #pragma unroll
        for (int m = 0; m < 16; m++) acc[m] += A[m*K + k] * bv;
    }
    #pragma unroll
    for (int o = 16; o > 0; o >>= 1)
        #pragma unroll
        for (int m = 0; m < 16; m++)
            acc[m] += __shfl_xor_sync(0xffffffffu, acc[m], o);
    __shared__ float red[4][16];
    if (lane == 0) {
        #pragma unroll
        for (int m = 0; m < 16; m++) red[w][m] = acc[m];
    }
    __syncthreads();
    if (tid < 16) {
        float v = red[0][tid] + red[1][tid] + red[2][tid] + red[3][tid] + bias[n];
        if (EPI == 2) v = gelu_exact(v);
        C[(size_t)tid*N + n] = v;
    }
}

// ---------------- embedding + layer-0 LN1 (fused) ----------------
__global__ void __launch_bounds__(256) embed_ln_kernel(
        const int* __restrict__ x, const int* __restrict__ level,
        const float* __restrict__ tok_emb, const float* __restrict__ level_emb,
        const float* __restrict__ te, float* __restrict__ h,
        const float* __restrict__ g, const float* __restrict__ b,
        __half* __restrict__ y) {
    int n = blockIdx.x;
    int bidx = n >> 9;
    int lvl = level[0];
    int tid = threadIdx.x;
    const float4* tk = (const float4*)(tok_emb + (size_t)x[n]*DD);
    const float4* le = (const float4*)(level_emb + (size_t)lvl*DD);
    const float4* tv = (const float4*)(te + (size_t)bidx*DD);
    float4 a = tk[tid], c = le[tid], d = tv[tid];
    float4 v = make_float4(a.x+c.x+d.x, a.y+c.y+d.y, a.z+c.z+d.z, a.w+c.w+d.w);
    ((float4*)(h + (size_t)n*DD))[tid] = v;

    float s  = v.x + v.y + v.z + v.w;
    float ss = v.x*v.x + v.y*v.y + v.z*v.z + v.w*v.w;
    __shared__ float sh1[8], sh2[8], shm[2];
    int lane = tid & 31, w = tid >> 5;
    #pragma unroll
    for (int o = 16; o > 0; o >>= 1) {
        s  += __shfl_xor_sync(0xffffffffu, s,  o);
        ss += __shfl_xor_sync(0xffffffffu, ss, o);
    }
    if (lane == 0) { sh1[w] = s; sh2[w] = ss; }
    __syncthreads();
    if (tid == 0) {
        float ts = 0.f, tss = 0.f;
        #pragma unroll
        for (int i = 0; i < 8; i++) { ts += sh1[i]; tss += sh2[i]; }
        float mean = ts * (1.0f/DD);
        float var  = tss * (1.0f/DD) - mean*mean;
        shm[0] = mean;
        shm[1] = rsqrtf(var + 1e-5f);
    }
    __syncthreads();
    float mean = shm[0], rs = shm[1];
    float4 gg = ((const float4*)g)[tid];
    float4 bb = ((const float4*)b)[tid];
    __half2* y2 = (__half2*)(y + (size_t)n*DD);
    y2[tid*2+0] = __floats2half2_rn((v.x-mean)*rs*gg.x + bb.x, (v.y-mean)*rs*gg.y + bb.y);
    y2[tid*2+1] = __floats2half2_rn((v.z-mean)*rs*gg.z + bb.z, (v.w-mean)*rs*gg.w + bb.w);
}

// ---------------- layernorm -> half out ----------------
__global__ void __launch_bounds__(256) layernorm_kernel(
        const float* __restrict__ x, const float* __restrict__ g,
        const float* __restrict__ b, __half* __restrict__ y) {
    size_t row = blockIdx.x;
    int tid = threadIdx.x;
    const float4* xr = (const float4*)(x + row*DD);
    float4 v = xr[tid];
    float s  = v.x + v.y + v.z + v.w;
    float ss = v.x*v.x + v.y*v.y + v.z*v.z + v.w*v.w;
    __shared__ float sh1[8], sh2[8], shm[2];
    int lane = tid & 31, w = tid >> 5;
    #pragma unroll
    for (int o = 16; o > 0; o >>= 1) {
        s  += __shfl_xor_sync(0xffffffffu, s,  o);
        ss += __shfl_xor_sync(0xffffffffu, ss, o);
    }
    if (lane == 0) { sh1[w] = s; sh2[w] = ss; }
    __syncthreads();
    if (tid == 0) {
        float ts = 0.f, tss = 0.f;
        #pragma unroll
        for (int i = 0; i < 8; i++) { ts += sh1[i]; tss += sh2[i]; }
        float mean = ts * (1.0f/DD);
        float var  = tss * (1.0f/DD) - mean*mean;
        shm[0] = mean;
        shm[1] = rsqrtf(var + 1e-5f);
    }
    __syncthreads();
    float mean = shm[0], rs = shm[1];
    float4 gg = ((const float4*)g)[tid];
    float4 bb = ((const float4*)b)[tid];
    __half2* y2 = (__half2*)(y + row*DD);
    y2[tid*2+0] = __floats2half2_rn((v.x-mean)*rs*gg.x + bb.x, (v.y-mean)*rs*gg.y + bb.y);
    y2[tid*2+1] = __floats2half2_rn((v.z-mean)*rs*gg.z + bb.z, (v.w-mean)*rs*gg.w + bb.w);
}

// ---------------- final layernorm + gather (t=1..511) -> half, padded ----
__global__ void __launch_bounds__(256) lnf_gather_kernel(
        const float* __restrict__ x, const float* __restrict__ g,
        const float* __restrict__ b, __half* __restrict__ y) {
    int m = blockIdx.x;          // 0..8191
    int tid = threadIdx.x;
    __half2* y2 = (__half2*)(y + (size_t)m*DD);
    if (m >= NHEADROWS) {
        __half2 z = __floats2half2_rn(0.f, 0.f);
        y2[tid*2+0] = z; y2[tid*2+1] = z;
        return;
    }
    int bb_ = m / TOUT, tt_ = m % TOUT + 1;
    size_t row = (size_t)(bb_*TT + tt_);
    const float4* xr = (const float4*)(x + row*DD);
    float4 v = xr[tid];
    float s  = v.x + v.y + v.z + v.w;
    float ss = v.x*v.x + v.y*v.y + v.z*v.z + v.w*v.w;
    __shared__ float sh1[8], sh2[8], shm[2];
    int lane = tid & 31, w = tid >> 5;
    #pragma unroll
    for (int o = 16; o > 0; o >>= 1) {
        s  += __shfl_xor_sync(0xffffffffu, s,  o);
        ss += __shfl_xor_sync(0xffffffffu, ss, o);
    }
    if (lane == 0) { sh1[w] = s; sh2[w] = ss; }
    __syncthreads();
    if (tid == 0) {
        float ts = 0.f, tss = 0.f;
        #pragma unroll
        for (int i = 0; i < 8; i++) { ts += sh1[i]; tss += sh2[i]; }
        float mean = ts * (1.0f/DD);
        float var  = tss * (1.0f/DD) - mean*mean;
        shm[0] = mean;
        shm[1] = rsqrtf(var + 1e-5f);
    }
    __syncthreads();
    float mean = shm[0], rs = shm[1];
    float4 gg = ((const float4*)g)[tid];
    float4 bb = ((const float4*)b)[tid];
    y2[tid*2+0] = __floats2half2_rn((v.x-mean)*rs*gg.x + bb.x, (v.y-mean)*rs*gg.y + bb.y);
    y2[tid*2+1] = __floats2half2_rn((v.z-mean)*rs*gg.z + bb.z, (v.w-mean)*rs*gg.w + bb.w);
}

// =======================================================================
// fp16 GEMM: C = A[M,K] @ BT[N,K]^T.  M%128==0, N%128==0, K%32==0.
// 128x128x32 tile, 3-buffer cp.async ring, 2 CTAs/SM.
// EPI: 0 = head (float out, stride NC, bounds), 1 = +residual(float out),
//      2 = gelu(half out), 3 = rope-qkv(half out, q*0.125)
// =======================================================================
#define HPITCH 40
#define HSTAGE 20480
#define HG_SMEM (3*HSTAGE)        // 61440 -> two CTAs fit per SM

template<int EPI>
__global__ void __launch_bounds__(256, 2) hgemm_kernel(
        const __half* __restrict__ A, const __half* __restrict__ BT,
        const float* __restrict__ Cres, void* __restrict__ Cv,
        int N, int K,
        const float* __restrict__ cosT, const float* __restrict__ sinT,
        int NC) {
    extern __shared__ __align__(16) char smem[];
    uint32_t sb = (uint32_t)__cvta_generic_to_shared(smem);
    int tid = threadIdx.x;
    int bn0 = blockIdx.x * 128, bm0 = blockIdx.y * 128;
    int wid = tid >> 5, lane = tid & 31;
    int wm = (wid & 3) * 32;
    int wn = (wid >> 2) * 64;
    int mc = lane >> 2;
    int kq2 = (lane & 3) * 2;

    float c[2][8][4];
    #pragma unroll
    for (int mt = 0; mt < 2; mt++)
        #pragma unroll
        for (int nt = 0; nt < 8; nt++)
            #pragma unroll
            for (int i = 0; i < 4; i++) c[mt][nt][i] = 0.f;

    int NIT = K >> 5;

    int a_r = lane & 15, a_c = (lane >> 4) * 8;
    int b_r = ((lane >> 4) << 3) + (lane & 7), b_c = ((lane >> 3) & 1) * 8;
    uint32_t aoff[2][2], boff[2][4];
    #pragma unroll
    for (int ks = 0; ks < 2; ks++) {
        #pragma unroll
        for (int mt = 0; mt < 2; mt++)
            aoff[ks][mt] = (uint32_t)((wm + mt*16 + a_r)*80 + (ks*16 + a_c)*2);
        #pragma unroll
        for (int p = 0; p < 4; p++)
            boff[ks][p] = (uint32_t)(10240 + (wn + p*16 + b_r)*80 + (ks*16 + b_c)*2);
    }

    auto load_stage = [&](int s, int buf) {
        int k0 = s << 5;
        uint32_t abase = sb + buf*HSTAGE;
        uint32_t bbase = abase + 10240;
        #pragma unroll
        for (int j = 0; j < 2; j++) {
            int ch = (tid << 1) + j;
            int row = ch >> 2, q = ch & 3;
            cp_async16(abase + row*80 + q*16, A + (size_t)(bm0 + row)*K + k0 + q*8);
        }
        #pragma unroll
        for (int j = 0; j < 2; j++) {
            int ch = (tid << 1) + j;
            int row = ch >> 2, q = ch & 3;
            cp_async16(bbase + row*80 + q*16, BT + (size_t)(bn0 + row)*K + k0 + q*8);
        }
    };

    load_stage(0, 0); asm volatile("cp.async.commit_group;");
    load_stage(1, 1); asm volatile("cp.async.commit_group;");

    int bufM = 0, bufL = 2;
    for (int it = 0; it < NIT; it++) {
        asm volatile("cp.async.wait_group 1;");
        __syncthreads();
        // buffer bufL was consumed in iteration it-1; every warp past the
        // barrier above has finished that MMA phase -> safe to refill now.
        if (it + 2 < NIT) load_stage(it + 2, bufL);
        asm volatile("cp.async.commit_group;");

        uint32_t stage = sb + bufM*HSTAGE;
        #pragma unroll
        for (int ks = 0; ks < 2; ks++) {
            uint32_t af[2][4], bf[8][2];
            LDSM_X4(af[0][0], af[0][1], af[0][2], af[0][3], stage + aoff[ks][0]);
            LDSM_X4(af[1][0], af[1][1], af[1][2], af[1][3], stage + aoff[ks][1]);
            #pragma unroll
            for (int p = 0; p < 4; p++)
                LDSM_X4(bf[2*p][0], bf[2*p][1], bf[2*p+1][0], bf[2*p+1][1],
                        stage + boff[ks][p]);
            #pragma unroll
            for (int mt = 0; mt < 2; mt++)
                #pragma unroll
                for (int nt = 0; nt < 8; nt++)
                    mma_f16(c[mt][nt], af[mt], bf[nt]);
        }
        bufL = bufM;
        bufM = (bufM == 2) ? 0 : bufM + 1;
    }

    // ---------------- epilogue ----------------
    #pragma unroll
    for (int mt = 0; mt < 2; mt++) {
        int r0 = bm0 + wm + mt*16 + mc;
        #pragma unroll
        for (int nt = 0; nt < 8; nt++) {
            int col = bn0 + wn + nt*8 + kq2;
            #pragma unroll
            for (int half_ = 0; half_ < 2; half_++) {
                int r = r0 + half_*8;
                float v0 = c[mt][nt][half_*2 + 0];
                float v1 = c[mt][nt][half_*2 + 1];
                if (EPI == 0) {
                    float* C = (float*)Cv;
                    if (r < NHEADROWS) {
                        if (col < NC)     C[(size_t)r*NC + col]     = v0;
                        if (col + 1 < NC) C[(size_t)r*NC + col + 1] = v1;
                    }
                } else if (EPI == 1) {
                    float* C = (float*)Cv;
                    const float2 res = *reinterpret_cast<const float2*>(Cres + (size_t)r*N + col);
                    v0 += res.x; v1 += res.y;
                    *reinterpret_cast<float2*>(C + (size_t)r*N + col) = make_float2(v0, v1);
                } else if (EPI == 2) {
                    __half* C = (__half*)Cv;
                    __half2 hv = __halves2half2(__float2half_rn(gelu_exact(v0)),
                                                __float2half_rn(gelu_exact(v1)));
                    *reinterpret_cast<__half2*>(C + (size_t)r*N + col) = hv;
                } else {   // EPI 3: rope on q/k pairs, q pre-scaled by 1/8 (exact)
                    __half* C = (__half*)Cv;
                    if (col < 2*DD) {
                        int j = (col & 63) >> 1;
                        int t = r & (TT-1);
                        float cc = cosT[t*32 + j], ssn = sinT[t*32 + j];
                        float x1 = v0, x2 = v1;
                        v0 = x1*cc - x2*ssn;
                        v1 = x1*ssn + x2*cc;
                        if (col < DD) { v0 *= 0.125f; v1 *= 0.125f; }
                    }
                    __half2 hv = __halves2half2(__float2half_rn(v0), __float2half_rn(v1));
                    *reinterpret_cast<__half2*>(C + (size_t)r*N + col) = hv;
                }
            }
        }
    }
}

// =======================================================================
// Flash attention: one block = 128 q rows x one (b,h). 8 warps (16 q each),
// online softmax in exp2/f16x2, row-sum via MMA-with-ones.
// Q fragments reloaded from smem per K-tile. 2 CTAs/SM.
// =======================================================================
#define FA_SMEM (128*144 + 2*64*144 + 2*64*144)   // 55296
#define LOG2E 1.4426950408889634f

__global__ void __launch_bounds__(256, 2) flash_attn_kernel(
        const __half* __restrict__ qkv, __half* __restrict__ o) {
    extern __shared__ __align__(16) char fsmem[];
    uint32_t sQ = (uint32_t)__cvta_generic_to_shared(fsmem);
    uint32_t sK = sQ + 128*144;
    uint32_t sV = sK + 2*64*144;
    int bh = blockIdx.y;
    int b = bh >> 4, h = bh & 15;
    int q0 = blockIdx.x * 128;
    int tid = threadIdx.x, wid = tid >> 5, lane = tid & 31;
    int mc = lane >> 2, kq2 = (lane & 3) * 2;

    auto load_kv = [&](int kc, int buf) {
        #pragma unroll
        for (int j = 0; j < 2; j++) {
            int ch = tid + j*256;
            int row = ch >> 3, seg = ch & 7;
            size_t base = (size_t)(b*TT + kc*64 + row)*3*DD + h*HDIM + seg*8;
            cp_async16(sK + buf*9216 + row*144 + seg*16, qkv + base + DD);
            cp_async16(sV + buf*9216 + row*144 + seg*16, qkv + base + 2*DD);
        }
    };

    #pragma unroll
    for (int j = 0; j < 4; j++) {
        int ch = tid + j*256;
        int row = ch >> 3, seg = ch & 7;
        cp_async16(sQ + row*144 + seg*16,
                   qkv + (size_t)(b*TT + q0 + row)*3*DD + h*HDIM + seg*8);
    }
    asm volatile("cp.async.commit_group;");
    load_kv(0, 0); asm volatile("cp.async.commit_group;");
    load_kv(1, 1); asm volatile("cp.async.commit_group;");

    asm volatile("cp.async.wait_group 2;");
    __syncthreads();

    uint32_t qb = sQ + (uint32_t)((wid*16 + (lane & 15))*144 + ((lane >> 4)*8)*2);

    uint32_t kRow = (uint32_t)(((lane >> 4) << 3) + (lane & 7));
    uint32_t kCol = (uint32_t)(((lane >> 3) & 1) * 8);
    uint32_t vRow = (uint32_t)(lane & 15);
    uint32_t vCol = (uint32_t)((lane >> 4) * 8);

    const uint32_t ONES2[2] = {0x3C003C00u, 0x3C003C00u};

    float m0 = -1e30f, m1 = -1e30f;
    float lc[4] = {0.f, 0.f, 0.f, 0.f};
    float oa[8][4];
    #pragma unroll
    for (int nt = 0; nt < 8; nt++)
        #pragma unroll
        for (int i = 0; i < 4; i++) oa[nt][i] = 0.f;

    for (int kc = 0; kc < 8; kc++) {
        asm volatile("cp.async.wait_group 1;");
        __syncthreads();
        uint32_t kb = sK + (kc & 1)*9216;
        uint32_t vb = sV + (kc & 1)*9216;

        float s[8][4];
        #pragma unroll
        for (int nt = 0; nt < 8; nt++)
            #pragma unroll
            for (int i = 0; i < 4; i++) s[nt][i] = 0.f;
        #pragma unroll
        for (int ks = 0; ks < 4; ks++) {
            uint32_t qf[4];
            LDSM_X4(qf[0], qf[1], qf[2], qf[3], qb + ks*32);
            uint32_t bf[8][2];
            #pragma unroll
            for (int p = 0; p < 4; p++)
                LDSM_X4(bf[2*p][0], bf[2*p][1], bf[2*p+1][0], bf[2*p+1][1],
                        kb + (p*16 + kRow)*144 + (ks*16 + kCol)*2);
            #pragma unroll
            for (int nt = 0; nt < 8; nt++) mma_f16(s[nt], qf, bf[nt]);
        }

        float mx0 = -1e30f, mx1 = -1e30f;
        #pragma unroll
        for (int nt = 0; nt < 8; nt++) {
            mx0 = fmaxf(mx0, fmaxf(s[nt][0], s[nt][1]));
            mx1 = fmaxf(mx1, fmaxf(s[nt][2], s[nt][3]));
        }
        mx0 = fmaxf(mx0, __shfl_xor_sync(0xffffffffu, mx0, 1));
        mx0 = fmaxf(mx0, __shfl_xor_sync(0xffffffffu, mx0, 2));
        mx1 = fmaxf(mx1, __shfl_xor_sync(0xffffffffu, mx1, 1));
        mx1 = fmaxf(mx1, __shfl_xor_sync(0xffffffffu, mx1, 2));
        float m0n = fmaxf(m0, mx0), m1n = fmaxf(m1, mx1);
        float a0 = __expf(m0 - m0n), a1 = __expf(m1 - m1n);
        float c0 = m0n * LOG2E, c1 = m1n * LOG2E;

        uint32_t pf[4][4];
        #pragma unroll
        for (int tp = 0; tp < 4; tp++) {
            pf[tp][0] = exp2h2(s[2*tp][0]  *LOG2E - c0, s[2*tp][1]  *LOG2E - c0);
            pf[tp][1] = exp2h2(s[2*tp][2]  *LOG2E - c1, s[2*tp][3]  *LOG2E - c1);
            pf[tp][2] = exp2h2(s[2*tp+1][0]*LOG2E - c0, s[2*tp+1][1]*LOG2E - c0);
            pf[tp][3] = exp2h2(s[2*tp+1][2]*LOG2E - c1, s[2*tp+1][3]*LOG2E - c1);
        }
        m0 = m0n; m1 = m1n;
        lc[0] *= a0; lc[1] *= a0; lc[2] *= a1; lc[3] *= a1;
        #pragma unroll
        for (int nt = 0; nt < 8; nt++) {
            oa[nt][0] *= a0; oa[nt][1] *= a0;
            oa[nt][2] *= a1; oa[nt][3] *= a1;
        }
        #pragma unroll
        for (int kt = 0; kt < 4; kt++) mma_f16(lc, pf[kt], ONES2);

        #pragma unroll
        for (int kt = 0; kt < 4; kt++) {
            #pragma unroll
            for (int p = 0; p < 4; p++) {
                uint32_t v0, v1, v2, v3;
                LDSM_X4T(v0, v1, v2, v3,
                         vb + (kt*16 + vRow)*144 + (p*16 + vCol)*2);
                uint32_t bv0[2] = {v0, v1}, bv1[2] = {v2, v3};
                mma_f16(oa[2*p],   pf[kt], bv0);
                mma_f16(oa[2*p+1], pf[kt], bv1);
            }
        }

        __syncthreads();
        if (kc + 2 < 8) load_kv(kc + 2, kc & 1);
        asm volatile("cp.async.commit_group;");
    }

    float i0 = 1.f / lc[0], i1 = 1.f / lc[2];
    int r0 = b*TT + q0 + wid*16 + mc;
    #pragma unroll
    for (int nt = 0; nt < 8; nt++) {
        int col = h*HDIM + nt*8 + kq2;
        *reinterpret_cast<__half2*>(o + (size_t)r0*DD + col) =
            __halves2half2(__float2half_rn(oa[nt][0]*i0), __float2half_rn(oa[nt][1]*i0));
        *reinterpret_cast<__half2*>(o + (size_t)(r0+8)*DD + col) =
            __halves2half2(__float2half_rn(oa[nt][2]*i1), __float2half_rn(oa[nt][3]*i1));
    }
}

// ---------------- host side ----------------
static inline int cdiv(int a, int b) { return (a + b - 1) / b; }

extern "C" void kernel_launch(void* const* d_in, const int* in_sizes, int n_in,
                              void* d_out, int out_size) {
    const int*   x         = (const int*)  d_in[0];
    const int*   t         = (const int*)  d_in[1];
    const int*   level     = (const int*)  d_in[2];
    const float* tok_emb   = (const float*)d_in[3];
    const float* level_emb = (const float*)d_in[4];
    const float* time_w1   = (const float*)d_in[5];
    const float* time_b1   = (const float*)d_in[6];
    const float* time_w2   = (const float*)d_in[7];
    const float* time_b2   = (const float*)d_in[8];
    const float* ln1_g     = (const float*)d_in[9];
    const float* ln1_b     = (const float*)d_in[10];
    const float* qkv_w     = (const float*)d_in[11];
    const float* proj_w    = (const float*)d_in[12];
    const float* ln2_g     = (const float*)d_in[13];
    const float* ln2_b     = (const float*)d_in[14];
    const float* fc1_w     = (const float*)d_in[15];
    const float* fc2_w     = (const float*)d_in[16];
    const float* lnf_g     = (const float*)d_in[17];
    const float* lnf_b     = (const float*)d_in[18];
    const float* head0_w   = (const float*)d_in[19];

    float  *ph, *ptein, *pteh, *pte, *pcos, *psin;
    __half *phnh, *pqkvh, *poh, *pffnh;
    __half *pqkvw, *pprojw, *pfc1w, *pfc2w, *pheadw;
    cudaGetSymbolAddress((void**)&ph,    g_h);
    cudaGetSymbolAddress((void**)&ptein, g_tein);
    cudaGetSymbolAddress((void**)&pteh,  g_teh);
    cudaGetSymbolAddress((void**)&pte,   g_te);
    cudaGetSymbolAddress((void**)&pcos,  g_cos);
    cudaGetSymbolAddress((void**)&psin,  g_sin);
    cudaGetSymbolAddress((void**)&phnh,  g_hnh);
    cudaGetSymbolAddress((void**)&pqkvh, g_qkvh);
    cudaGetSymbolAddress((void**)&poh,   g_oh);
    cudaGetSymbolAddress((void**)&pffnh, g_ffnh);
    cudaGetSymbolAddress((void**)&pqkvw, g_qkvw);
    cudaGetSymbolAddress((void**)&pprojw,g_projw);
    cudaGetSymbolAddress((void**)&pfc1w, g_fc1w);
    cudaGetSymbolAddress((void**)&pfc2w, g_fc2w);
    cudaGetSymbolAddress((void**)&pheadw,g_headw);

    cudaFuncSetAttribute(hgemm_kernel<0>, cudaFuncAttributeMaxDynamicSharedMemorySize, HG_SMEM);
    cudaFuncSetAttribute(hgemm_kernel<1>, cudaFuncAttributeMaxDynamicSharedMemorySize, HG_SMEM);
    cudaFuncSetAttribute(hgemm_kernel<2>, cudaFuncAttributeMaxDynamicSharedMemorySize, HG_SMEM);
    cudaFuncSetAttribute(hgemm_kernel<3>, cudaFuncAttributeMaxDynamicSharedMemorySize, HG_SMEM);
    cudaFuncSetAttribute(flash_attn_kernel, cudaFuncAttributeMaxDynamicSharedMemorySize, FA_SMEM);

    dim3 blk(256);
    dim3 tb(32, 8);

    te_in_kernel<<<BB, 512>>>(t, ptein);
    tgemm_kernel<2><<<DFF, 128>>>(ptein, time_w1, time_b1, pteh, DD, DFF);
    tgemm_kernel<0><<<DD, 128>>>(pteh, time_w2, time_b2, pte, DFF, DD);
    prep_kernel<<<P2_TOTAL, tb>>>(qkv_w, proj_w, fc1_w, fc2_w, head0_w,
                                  pqkvw, pprojw, pfc1w, pfc2w, pheadw,
                                  pcos, psin);
    embed_ln_kernel<<<NTOK, 256>>>(x, level, tok_emb, level_emb, pte, ph,
                                   ln1_g, ln1_b, phnh);

    for (int i = 0; i < LL; i++) {
        hgemm_kernel<3><<<dim3(3*DD/128, NTOK/128), blk, HG_SMEM>>>(
            phnh, pqkvw + (size_t)i*DD*3*DD, nullptr, pqkvh, 3*DD, DD, pcos, psin, 0);

        flash_attn_kernel<<<dim3(TT/128, BB*HH), 256, FA_SMEM>>>(pqkvh, poh);

        hgemm_kernel<1><<<dim3(DD/128, NTOK/128), blk, HG_SMEM>>>(
            poh, pprojw + (size_t)i*DD*DD, ph, ph, DD, DD, pcos, psin, 0);

        layernorm_kernel<<<NTOK, 256>>>(ph, ln2_g + i*DD, ln2_b + i*DD, phnh);

        hgemm_kernel<2><<<dim3(DFF/128, NTOK/128), blk, HG_SMEM>>>(
            phnh, pfc1w + (size_t)i*DD*DFF, nullptr, pffnh, DFF, DD, pcos, psin, 0);

        hgemm_kernel<1><<<dim3(DD/128, NTOK/128), blk, HG_SMEM>>>(
            pffnh, pfc2w + (size_t)i*DFF*DD, ph, ph, DD, DFF, pcos, psin, 0);

        if (i + 1 < LL)
            layernorm_kernel<<<NTOK, 256>>>(ph, ln1_g + (i+1)*DD, ln1_b + (i+1)*DD, phnh);
    }

    // final LN fused with gather (zero-padded to 8192 rows), fp16 head GEMM
    lnf_gather_kernel<<<NTOK, 256>>>(ph, lnf_g, lnf_b, phnh);
    hgemm_kernel<0><<<dim3(NHPAD/128, NTOK/128), blk, HG_SMEM>>>(
        phnh, pheadw, nullptr, (float*)d_out, NHPAD, DD, pcos, psin, V0);
}